// round 1
// baseline (speedup 1.0000x reference)
#include <cuda_runtime.h>

// Problem constants
#define BB   8
#define QQ   256
#define KK   1024
#define DD   256
#define HH   128
#define DVV  128
#define LOG2E 1.44269504088896340736f

// Scratch (allocation-free: device globals)
__device__ float g_WqT[HH * DD];       // [h][d]
__device__ float g_WkT[HH * DD];       // [h][d]
__device__ float g_Eq [BB * QQ * HH];  // [b][q][h]  = exp(2*qproj)
__device__ float g_EkT[BB * HH * KK];  // [b][h][k]  = exp(2*kproj), transposed

__device__ __forceinline__ float frcp(float x) {
    float r; asm("rcp.approx.f32 %0, %1;" : "=f"(r) : "f"(x)); return r;
}
__device__ __forceinline__ float fex2(float x) {
    float r; asm("ex2.approx.f32 %0, %1;" : "=f"(r) : "f"(x)); return r;
}

// ---------------------------------------------------------------------------
// Kernel 1: transpose W_q, W_k ([D,H] -> [H,D]) so projection reads are vec4.
// ---------------------------------------------------------------------------
__global__ void transpose_w(const float* __restrict__ Wq,
                            const float* __restrict__ Wk) {
    int i = blockIdx.x * 256 + threadIdx.x;          // over H*D = 32768
    if (i < HH * DD) {
        int h = i / DD, d = i % DD;
        g_WqT[i] = Wq[d * HH + h];
        g_WkT[i] = Wk[d * HH + h];
    }
}

// ---------------------------------------------------------------------------
// Kernel 2: projection + exp.  4 rows per block, thread = output column h.
//   isK=0: rows are queries [B*Q, D] -> g_Eq[row][h]
//   isK=1: rows are keys    [B*K, D] -> g_EkT[b][h][k]  (transposed store)
// ---------------------------------------------------------------------------
__global__ __launch_bounds__(128)
void proj_kernel(const float* __restrict__ X, int isK) {
    __shared__ __align__(16) float xs[4][DD];
    int row0 = blockIdx.x * 4;
    int tid  = threadIdx.x;   // 0..127 (= h)

    // load 4 contiguous input rows (coalesced)
    for (int i = tid; i < 4 * DD; i += 128)
        xs[i >> 8][i & 255] = X[row0 * DD + i];
    __syncthreads();

    const float* WT = isK ? g_WkT : g_WqT;
    const float4* w4 = (const float4*)(WT + tid * DD);

    float acc[4] = {0.f, 0.f, 0.f, 0.f};
#pragma unroll 8
    for (int d4 = 0; d4 < DD / 4; d4++) {
        float4 wv = w4[d4];
#pragma unroll
        for (int r = 0; r < 4; r++) {
            float4 x = *(const float4*)&xs[r][d4 * 4];
            acc[r] = fmaf(x.x, wv.x,
                     fmaf(x.y, wv.y,
                     fmaf(x.z, wv.z,
                     fmaf(x.w, wv.w, acc[r]))));
        }
    }
#pragma unroll
    for (int r = 0; r < 4; r++) {
        float e = fex2(acc[r] * (2.0f * LOG2E));   // e^{2*proj}
        int row = row0 + r;
        if (isK) {
            int b = row >> 10, k = row & 1023;
            g_EkT[(b * HH + tid) * KK + k] = e;
        } else {
            g_Eq[row * HH + tid] = e;
        }
    }
}

// ---------------------------------------------------------------------------
// Kernel 3: fused scores + masked softmax + attn@V.
// Block = (b, tile of 4 q-rows). 256 threads.
//   score(b,q,k) = sum_h w_h * tanh(qp+kp)
//                = Wsum - sum_h (2 w_h) * rcp(1 + Eq[h]*Ek[h])
// ---------------------------------------------------------------------------
__global__ __launch_bounds__(256)
void attn_kernel(const float* __restrict__ values,
                 const int*   __restrict__ valid_lens,
                 const float* __restrict__ w_v,
                 float*       __restrict__ out) {
    __shared__ __align__(16) float s_eq[HH][4];        // [h][q]
    __shared__ float s_w2[HH];                         // -2*w_v[h]
    __shared__ __align__(16) float s_scores[KK * 4];   // [k][q]
    __shared__ __align__(16) float s_part[4][4][DVV];  // [kgroup][q][v]
    __shared__ float s_red[8][4];
    __shared__ float s_mx[4];
    __shared__ float s_rden[4];
    __shared__ float s_wsum;

    int b  = blockIdx.x >> 6;        // 8 * 64 blocks
    int q0 = (blockIdx.x & 63) * 4;
    int tid = threadIdx.x;
    int len = valid_lens[b];

    if (tid < HH) s_w2[tid] = -2.0f * w_v[tid];
    // Eq tile -> smem, [h][q] layout (LDS.128 gets 4 q at once)
    for (int i = tid; i < 4 * HH; i += 256) {
        int qq = i >> 7, h = i & 127;
        s_eq[h][qq] = g_Eq[((b * QQ) + q0 + qq) * HH + h];
    }
    __syncthreads();
    if (tid == 0) {
        float s = 0.f;
        for (int h = 0; h < HH; h++) s += s_w2[h];
        s_wsum = -0.5f * s;                           // = sum(w_v)
    }
    __syncthreads();

    // ---- main loop: scores ----
    int k0 = tid * 4;
    float acc[4][4];                                  // [kk][q]
#pragma unroll
    for (int kk = 0; kk < 4; kk++)
#pragma unroll
        for (int qq = 0; qq < 4; qq++) acc[kk][qq] = 0.f;

    if (k0 < len) {
        const float* ekbase = g_EkT + (size_t)b * HH * KK + k0;
#pragma unroll 4
        for (int h = 0; h < HH; h++) {
            float4 ek = *(const float4*)(ekbase + h * KK);
            float4 eqv = *(const float4*)&s_eq[h][0];
            float w = s_w2[h];
            float eka[4] = {ek.x, ek.y, ek.z, ek.w};
            float eqa[4] = {eqv.x, eqv.y, eqv.z, eqv.w};
#pragma unroll
            for (int kk = 0; kk < 4; kk++)
#pragma unroll
                for (int qq = 0; qq < 4; qq++) {
                    float E = fmaf(eka[kk], eqa[qq], 1.0f);
                    acc[kk][qq] = fmaf(w, frcp(E), acc[kk][qq]);
                }
        }
        float ws = s_wsum;
#pragma unroll
        for (int kk = 0; kk < 4; kk++) {
            float4 sc = make_float4(ws + acc[kk][0], ws + acc[kk][1],
                                    ws + acc[kk][2], ws + acc[kk][3]);
            *(float4*)&s_scores[(k0 + kk) * 4] = sc;
        }
    }
    __syncthreads();

    // ---- masked softmax over k < len (unnormalized; denom folded later) ----
    int warp = tid >> 5, lane = tid & 31;
    float mx[4] = {-3.0e38f, -3.0e38f, -3.0e38f, -3.0e38f};
    for (int k = tid; k < len; k += 256) {
        float4 sc = *(const float4*)&s_scores[k * 4];
        mx[0] = fmaxf(mx[0], sc.x); mx[1] = fmaxf(mx[1], sc.y);
        mx[2] = fmaxf(mx[2], sc.z); mx[3] = fmaxf(mx[3], sc.w);
    }
#pragma unroll
    for (int qq = 0; qq < 4; qq++)
        for (int o = 16; o > 0; o >>= 1)
            mx[qq] = fmaxf(mx[qq], __shfl_xor_sync(0xffffffffu, mx[qq], o));
    if (lane == 0)
#pragma unroll
        for (int qq = 0; qq < 4; qq++) s_red[warp][qq] = mx[qq];
    __syncthreads();
    if (tid < 4) {
        float m = s_red[0][tid];
        for (int w = 1; w < 8; w++) m = fmaxf(m, s_red[w][tid]);
        s_mx[tid] = m;
    }
    __syncthreads();

    float sm[4] = {0.f, 0.f, 0.f, 0.f};
    float m0 = s_mx[0], m1 = s_mx[1], m2 = s_mx[2], m3 = s_mx[3];
    for (int k = tid; k < len; k += 256) {
        float4 sc = *(const float4*)&s_scores[k * 4];
        sc.x = fex2((sc.x - m0) * LOG2E);
        sc.y = fex2((sc.y - m1) * LOG2E);
        sc.z = fex2((sc.z - m2) * LOG2E);
        sc.w = fex2((sc.w - m3) * LOG2E);
        sm[0] += sc.x; sm[1] += sc.y; sm[2] += sc.z; sm[3] += sc.w;
        *(float4*)&s_scores[k * 4] = sc;
    }
#pragma unroll
    for (int qq = 0; qq < 4; qq++)
        for (int o = 16; o > 0; o >>= 1)
            sm[qq] += __shfl_xor_sync(0xffffffffu, sm[qq], o);
    if (lane == 0)
#pragma unroll
        for (int qq = 0; qq < 4; qq++) s_red[warp][qq] = sm[qq];
    __syncthreads();
    if (tid < 4) {
        float s = 0.f;
        for (int w = 0; w < 8; w++) s += s_red[w][tid];
        s_rden[tid] = frcp(s);
    }
    __syncthreads();

    // ---- attn @ V  (k split into 4 strided groups, reduce via smem) ----
    int g = tid >> 6;          // k-group
    int l = tid & 63;          // v pair index: v0 = 2*l
    float2 a[4];
#pragma unroll
    for (int qq = 0; qq < 4; qq++) { a[qq].x = 0.f; a[qq].y = 0.f; }
    const float2* Vp = (const float2*)(values + (size_t)b * KK * DVV);
    for (int k = g; k < len; k += 4) {
        float4 p = *(const float4*)&s_scores[k * 4];
        float2 v = Vp[k * (DVV / 2) + l];
        a[0].x = fmaf(p.x, v.x, a[0].x); a[0].y = fmaf(p.x, v.y, a[0].y);
        a[1].x = fmaf(p.y, v.x, a[1].x); a[1].y = fmaf(p.y, v.y, a[1].y);
        a[2].x = fmaf(p.z, v.x, a[2].x); a[2].y = fmaf(p.z, v.y, a[2].y);
        a[3].x = fmaf(p.w, v.x, a[3].x); a[3].y = fmaf(p.w, v.y, a[3].y);
    }
#pragma unroll
    for (int qq = 0; qq < 4; qq++)
        *(float2*)&s_part[g][qq][2 * l] = a[qq];
    __syncthreads();

    // final combine: thread t -> (q = t>>6, v0 = (t&63)*2)
    {
        int qq = tid >> 6;
        int v0 = (tid & 63) * 2;
        float rd = s_rden[qq];
        float ox = 0.f, oy = 0.f;
#pragma unroll
        for (int gg = 0; gg < 4; gg++) {
            ox += s_part[gg][qq][v0];
            oy += s_part[gg][qq][v0 + 1];
        }
        float2 o = make_float2(ox * rd, oy * rd);
        *(float2*)&out[((size_t)(b * QQ + q0 + qq)) * DVV + v0] = o;
    }
}

// ---------------------------------------------------------------------------
extern "C" void kernel_launch(void* const* d_in, const int* in_sizes, int n_in,
                              void* d_out, int out_size) {
    const float* queries = (const float*)d_in[0];   // [8,256,256]
    const float* keys    = (const float*)d_in[1];   // [8,1024,256]
    const float* values  = (const float*)d_in[2];   // [8,1024,128]
    const int*   vlens   = (const int*)  d_in[3];   // [8]
    const float* W_q     = (const float*)d_in[4];   // [256,128]
    const float* W_k     = (const float*)d_in[5];   // [256,128]
    const float* w_v     = (const float*)d_in[6];   // [128]
    float* out = (float*)d_out;                     // [8,256,128]

    transpose_w<<<(HH * DD + 255) / 256, 256>>>(W_q, W_k);
    proj_kernel<<<(BB * QQ) / 4, 128>>>(queries, 0);
    proj_kernel<<<(BB * KK) / 4, 128>>>(keys, 1);
    attn_kernel<<<BB * (QQ / 4), 256>>>(values, vlens, w_v, out);
}

// round 2
// speedup vs baseline: 1.0406x; 1.0406x over previous
#include <cuda_runtime.h>

#define BB   8
#define QQ   256
#define KK   1024
#define DD   256
#define HH   128
#define DVV  128
#define LOG2E 1.44269504088896340736f

__device__ float g_WqT[HH * DD];       // [h][d]
__device__ float g_WkT[HH * DD];       // [h][d]
__device__ float g_Eq [BB * QQ * HH];  // [b][q][h]  = exp(2*qproj)
__device__ float g_EkT[BB * HH * KK];  // [b][h][k]  = exp(2*kproj), transposed
__device__ float g_w2 [HH];            // -2*w_v[h]
__device__ float g_wsum;               // sum(w_v)

__device__ __forceinline__ float frcp(float x) {
    float r; asm("rcp.approx.f32 %0, %1;" : "=f"(r) : "f"(x)); return r;
}
__device__ __forceinline__ float fex2(float x) {
    float r; asm("ex2.approx.f32 %0, %1;" : "=f"(r) : "f"(x)); return r;
}

// ---------------------------------------------------------------------------
// Kernel 1: transpose W_q, W_k ([D,H] -> [H,D]); block 0 also prepares
// w2[h] = -2*w_v[h] and wsum = sum(w_v).
// ---------------------------------------------------------------------------
__global__ void transpose_w(const float* __restrict__ Wq,
                            const float* __restrict__ Wk,
                            const float* __restrict__ w_v) {
    int i = blockIdx.x * 256 + threadIdx.x;          // over H*D = 32768
    if (i < HH * DD) {
        int h = i / DD, d = i % DD;
        g_WqT[i] = Wq[d * HH + h];
        g_WkT[i] = Wk[d * HH + h];
    }
    if (blockIdx.x == 0) {
        if (threadIdx.x < HH) g_w2[threadIdx.x] = -2.0f * w_v[threadIdx.x];
        if (threadIdx.x == 0) {
            float s = 0.f;
            for (int h = 0; h < HH; h++) s += w_v[h];
            g_wsum = s;
        }
    }
}

// ---------------------------------------------------------------------------
// Kernel 2: merged projection + exp. 4 rows per block, thread = column h.
// ---------------------------------------------------------------------------
__global__ __launch_bounds__(128)
void proj_kernel(const float* __restrict__ Q, const float* __restrict__ Kx) {
    __shared__ __align__(16) float xs[4][DD];
    int blk  = blockIdx.x;
    bool isK = blk >= (BB * QQ) / 4;
    int row0 = isK ? (blk - (BB * QQ) / 4) * 4 : blk * 4;
    const float* X = isK ? Kx : Q;
    int tid  = threadIdx.x;   // 0..127 (= h)

    for (int i = tid; i < 4 * DD; i += 128)
        xs[i >> 8][i & 255] = X[(size_t)row0 * DD + i];
    __syncthreads();

    const float* WT = isK ? g_WkT : g_WqT;
    const float4* w4 = (const float4*)(WT + tid * DD);

    float4 a4[4];
#pragma unroll
    for (int r = 0; r < 4; r++) a4[r] = make_float4(0.f, 0.f, 0.f, 0.f);

#pragma unroll 4
    for (int d4 = 0; d4 < DD / 4; d4++) {
        float4 wv = w4[d4];
#pragma unroll
        for (int r = 0; r < 4; r++) {
            float4 x = *(const float4*)&xs[r][d4 * 4];
            a4[r].x = fmaf(x.x, wv.x, a4[r].x);
            a4[r].y = fmaf(x.y, wv.y, a4[r].y);
            a4[r].z = fmaf(x.z, wv.z, a4[r].z);
            a4[r].w = fmaf(x.w, wv.w, a4[r].w);
        }
    }
#pragma unroll
    for (int r = 0; r < 4; r++) {
        float acc = (a4[r].x + a4[r].y) + (a4[r].z + a4[r].w);
        float e = fex2(acc * (2.0f * LOG2E));   // e^{2*proj}
        int row = row0 + r;
        if (isK) {
            int b = row >> 10, k = row & 1023;
            g_EkT[(b * HH + tid) * KK + k] = e;
        } else {
            g_Eq[row * HH + tid] = e;
        }
    }
}

// ---------------------------------------------------------------------------
// Kernel 3: fused scores + masked softmax + attn@V.
// ---------------------------------------------------------------------------
__global__ __launch_bounds__(256)
void attn_kernel(const float* __restrict__ values,
                 const int*   __restrict__ valid_lens,
                 float*       __restrict__ out) {
    __shared__ __align__(16) float s_eq[HH][4];        // [h][q]
    __shared__ __align__(16) float s_w2[HH];           // -2*w_v[h]
    __shared__ __align__(16) float s_scores[KK * 4];   // [k][q]
    __shared__ __align__(16) float s_part[4][4][DVV];  // [kgroup][q][v]
    __shared__ float s_red[8][4];
    __shared__ float s_mx[4];
    __shared__ float s_rden[4];

    int b  = blockIdx.x & 7;                // interleave batches across waves
    int q0 = (blockIdx.x >> 3) * 4;
    int tid = threadIdx.x;
    int len = valid_lens[b];
    float ws = g_wsum;

    if (tid < HH) s_w2[tid] = g_w2[tid];
    for (int i = tid; i < 4 * HH; i += 256) {
        int qq = i >> 7, h = i & 127;
        s_eq[h][qq] = g_Eq[((b * QQ) + q0 + qq) * HH + h];
    }
    __syncthreads();

    // ---- main loop: scores (k chunks of 512, 2 k per thread, h-paired) ----
    for (int kbase = 0; kbase < len; kbase += 512) {
        int k0 = kbase + tid * 2;
        if (k0 < len) {
            float accx[4] = {0.f, 0.f, 0.f, 0.f};
            float accy[4] = {0.f, 0.f, 0.f, 0.f};
            const float* ekb = g_EkT + ((size_t)b * HH) * KK + k0;
#pragma unroll 2
            for (int h = 0; h < HH; h += 2) {
                float2 ekA = *(const float2*)(ekb + h * KK);
                float2 ekB = *(const float2*)(ekb + (h + 1) * KK);
                float4 eqA = *(const float4*)s_eq[h];
                float4 eqB = *(const float4*)s_eq[h + 1];
                float2 w   = *(const float2*)&s_w2[h];
                float eqAa[4] = {eqA.x, eqA.y, eqA.z, eqA.w};
                float eqBa[4] = {eqB.x, eqB.y, eqB.z, eqB.w};
#pragma unroll
                for (int qq = 0; qq < 4; qq++) {
                    float E1 = fmaf(ekA.x, eqAa[qq], 1.0f);
                    float E2 = fmaf(ekB.x, eqBa[qq], 1.0f);
                    float num = fmaf(w.x, E2, w.y * E1);
                    accx[qq] = fmaf(num, frcp(E1 * E2), accx[qq]);
                    float F1 = fmaf(ekA.y, eqAa[qq], 1.0f);
                    float F2 = fmaf(ekB.y, eqBa[qq], 1.0f);
                    float num2 = fmaf(w.x, F2, w.y * F1);
                    accy[qq] = fmaf(num2, frcp(F1 * F2), accy[qq]);
                }
            }
            float4 scx = make_float4(ws + accx[0], ws + accx[1],
                                     ws + accx[2], ws + accx[3]);
            float4 scy = make_float4(ws + accy[0], ws + accy[1],
                                     ws + accy[2], ws + accy[3]);
            *(float4*)&s_scores[k0 * 4]       = scx;
            *(float4*)&s_scores[(k0 + 1) * 4] = scy;
        }
    }
    __syncthreads();

    // ---- masked softmax over k < len (unnormalized) ----
    int warp = tid >> 5, lane = tid & 31;
    float mx[4] = {-3.0e38f, -3.0e38f, -3.0e38f, -3.0e38f};
    for (int k = tid; k < len; k += 256) {
        float4 sc = *(const float4*)&s_scores[k * 4];
        mx[0] = fmaxf(mx[0], sc.x); mx[1] = fmaxf(mx[1], sc.y);
        mx[2] = fmaxf(mx[2], sc.z); mx[3] = fmaxf(mx[3], sc.w);
    }
#pragma unroll
    for (int qq = 0; qq < 4; qq++)
        for (int o = 16; o > 0; o >>= 1)
            mx[qq] = fmaxf(mx[qq], __shfl_xor_sync(0xffffffffu, mx[qq], o));
    if (lane == 0)
#pragma unroll
        for (int qq = 0; qq < 4; qq++) s_red[warp][qq] = mx[qq];
    __syncthreads();
    if (tid < 4) {
        float m = s_red[0][tid];
        for (int w = 1; w < 8; w++) m = fmaxf(m, s_red[w][tid]);
        s_mx[tid] = m;
    }
    __syncthreads();

    float sm[4] = {0.f, 0.f, 0.f, 0.f};
    float m0 = s_mx[0], m1 = s_mx[1], m2 = s_mx[2], m3 = s_mx[3];
    for (int k = tid; k < len; k += 256) {
        float4 sc = *(const float4*)&s_scores[k * 4];
        sc.x = fex2((sc.x - m0) * LOG2E);
        sc.y = fex2((sc.y - m1) * LOG2E);
        sc.z = fex2((sc.z - m2) * LOG2E);
        sc.w = fex2((sc.w - m3) * LOG2E);
        sm[0] += sc.x; sm[1] += sc.y; sm[2] += sc.z; sm[3] += sc.w;
        *(float4*)&s_scores[k * 4] = sc;
    }
#pragma unroll
    for (int qq = 0; qq < 4; qq++)
        for (int o = 16; o > 0; o >>= 1)
            sm[qq] += __shfl_xor_sync(0xffffffffu, sm[qq], o);
    if (lane == 0)
#pragma unroll
        for (int qq = 0; qq < 4; qq++) s_red[warp][qq] = sm[qq];
    __syncthreads();
    if (tid < 4) {
        float s = 0.f;
        for (int w = 0; w < 8; w++) s += s_red[w][tid];
        s_rden[tid] = frcp(s);
    }
    __syncthreads();

    // ---- attn @ V ----
    int g = tid >> 6;          // k-group
    int l = tid & 63;          // v pair index
    float2 a[4];
#pragma unroll
    for (int qq = 0; qq < 4; qq++) { a[qq].x = 0.f; a[qq].y = 0.f; }
    const float2* Vp = (const float2*)(values + (size_t)b * KK * DVV);
    for (int k = g; k < len; k += 4) {
        float4 p = *(const float4*)&s_scores[k * 4];
        float2 v = Vp[k * (DVV / 2) + l];
        a[0].x = fmaf(p.x, v.x, a[0].x); a[0].y = fmaf(p.x, v.y, a[0].y);
        a[1].x = fmaf(p.y, v.x, a[1].x); a[1].y = fmaf(p.y, v.y, a[1].y);
        a[2].x = fmaf(p.z, v.x, a[2].x); a[2].y = fmaf(p.z, v.y, a[2].y);
        a[3].x = fmaf(p.w, v.x, a[3].x); a[3].y = fmaf(p.w, v.y, a[3].y);
    }
#pragma unroll
    for (int qq = 0; qq < 4; qq++)
        *(float2*)&s_part[g][qq][2 * l] = a[qq];
    __syncthreads();

    {
        int qq = tid >> 6;
        int v0 = (tid & 63) * 2;
        float rd = s_rden[qq];
        float ox = 0.f, oy = 0.f;
#pragma unroll
        for (int gg = 0; gg < 4; gg++) {
            ox += s_part[gg][qq][v0];
            oy += s_part[gg][qq][v0 + 1];
        }
        float2 o = make_float2(ox * rd, oy * rd);
        *(float2*)&out[((size_t)(b * QQ + q0 + qq)) * DVV + v0] = o;
    }
}

extern "C" void kernel_launch(void* const* d_in, const int* in_sizes, int n_in,
                              void* d_out, int out_size) {
    const float* queries = (const float*)d_in[0];   // [8,256,256]
    const float* keys    = (const float*)d_in[1];   // [8,1024,256]
    const float* values  = (const float*)d_in[2];   // [8,1024,128]
    const int*   vlens   = (const int*)  d_in[3];   // [8]
    const float* W_q     = (const float*)d_in[4];   // [256,128]
    const float* W_k     = (const float*)d_in[5];   // [256,128]
    const float* w_v     = (const float*)d_in[6];   // [128]
    float* out = (float*)d_out;                     // [8,256,128]

    transpose_w<<<(HH * DD + 255) / 256, 256>>>(W_q, W_k, w_v);
    proj_kernel<<<(BB * QQ + BB * KK) / 4, 128>>>(queries, keys);
    attn_kernel<<<BB * (QQ / 4), 256>>>(values, vlens, out);
}

// round 3
// speedup vs baseline: 1.5819x; 1.5203x over previous
#include <cuda_runtime.h>

#define BB   8
#define QQ   256
#define KK   1024
#define DD   256
#define HH   128
#define DVV  128
#define LOG2E 1.44269504088896340736f

// Scratch (allocation-free: device globals)
__device__ float g_Eq [BB * QQ * HH];  // [b][q][h]  = exp(2*qproj)
__device__ float g_EkT[BB * HH * KK];  // [b][h][k]  = exp(2*kproj), transposed

__device__ __forceinline__ float frcp(float x) {
    float r; asm("rcp.approx.f32 %0, %1;" : "=f"(r) : "f"(x)); return r;
}
__device__ __forceinline__ float fex2(float x) {
    float r; asm("ex2.approx.f32 %0, %1;" : "=f"(r) : "f"(x)); return r;
}

// ---------------------------------------------------------------------------
// Kernel 1: merged projection + exp. 8 rows per block, thread = column h.
// W read in NATIVE [d][h] layout: thread tid = h -> perfectly coalesced LDG.
//   blocks [0,256)    : query rows -> g_Eq[row][h]
//   blocks [256,1280) : key rows   -> g_EkT[b][h][k] (smem-transposed store)
// ---------------------------------------------------------------------------
__global__ __launch_bounds__(128)
void proj_kernel(const float* __restrict__ Q, const float* __restrict__ Kx,
                 const float* __restrict__ Wq, const float* __restrict__ Wk) {
    __shared__ __align__(16) float xs[8][DD];   // 8 input rows
    __shared__ float es[HH][8];                 // exp results for K transpose
    int blk  = blockIdx.x;
    bool isK = blk >= (BB * QQ) / 8;            // >= 256
    int rowbase = isK ? (blk - (BB * QQ) / 8) * 8 : blk * 8;
    const float* X = isK ? Kx : Q;
    const float* W = isK ? Wk : Wq;
    int tid = threadIdx.x;                      // 0..127 (= h)

    for (int i = tid; i < 8 * DD; i += 128)
        xs[i >> 8][i & 255] = X[(size_t)rowbase * DD + i];
    __syncthreads();

    float acc[8];
#pragma unroll
    for (int r = 0; r < 8; r++) acc[r] = 0.f;

#pragma unroll 2
    for (int d4 = 0; d4 < DD / 4; d4++) {
        int d = d4 * 4;
        float w0 = W[(d + 0) * HH + tid];       // coalesced across warp
        float w1 = W[(d + 1) * HH + tid];
        float w2 = W[(d + 2) * HH + tid];
        float w3 = W[(d + 3) * HH + tid];
#pragma unroll
        for (int r = 0; r < 8; r++) {
            float4 x = *(const float4*)&xs[r][d];  // broadcast LDS.128
            acc[r] = fmaf(x.x, w0, acc[r]);
            acc[r] = fmaf(x.y, w1, acc[r]);
            acc[r] = fmaf(x.z, w2, acc[r]);
            acc[r] = fmaf(x.w, w3, acc[r]);
        }
    }

    if (!isK) {
#pragma unroll
        for (int r = 0; r < 8; r++)
            g_Eq[(rowbase + r) * HH + tid] = fex2(acc[r] * (2.0f * LOG2E));
    } else {
#pragma unroll
        for (int r = 0; r < 8; r++)
            es[tid][r] = fex2(acc[r] * (2.0f * LOG2E));
        __syncthreads();
        int b  = rowbase >> 10;
        int k0 = rowbase & 1023;
        for (int i = tid; i < HH * 8; i += 128) {
            int h = i >> 3, r = i & 7;
            g_EkT[((size_t)b * HH + h) * KK + k0 + r] = es[h][r];
        }
    }
}

// ---------------------------------------------------------------------------
// Kernel 2: fused scores + masked softmax + attn@V.
// Block = (b, tile of 2 q-rows), 1024 blocks, 256 threads.
// score(b,q,k) = wsum - sum_h (2 w_h) * rcp(1 + Eq*Ek); wsum is a global
// constant -> cancels in softmax, so we accumulate only the sum term.
// h-pairing: w1/E1 + w2/E2 = (w1*E2 + w2*E1) * rcp(E1*E2) (halves MUFU load).
// k in chunks of 512 (2 k per thread); chunks beyond len skipped.
// ---------------------------------------------------------------------------
__global__ __launch_bounds__(256)
void attn_kernel(const float* __restrict__ values,
                 const int*   __restrict__ valid_lens,
                 const float* __restrict__ w_v,
                 float*       __restrict__ out) {
    __shared__ __align__(16) float s_eq[HH][2];        // [h][q]
    __shared__ __align__(16) float s_w2[HH];           // -2*w_v[h]
    __shared__ __align__(16) float s_scores[KK * 2];   // [k][q]
    __shared__ __align__(16) float s_part[4][2][DVV];  // [kgroup][q][v]
    __shared__ float s_red[8][2];
    __shared__ float s_mx[2];
    __shared__ float s_rden[2];

    int b  = blockIdx.x & 7;                // interleave batches across waves
    int q0 = (blockIdx.x >> 3) * 2;
    int tid = threadIdx.x;
    int len = valid_lens[b];

    if (tid < HH) s_w2[tid] = -2.0f * w_v[tid];
    if (tid < 2 * HH) {
        int qq = tid >> 7, h = tid & 127;
        s_eq[h][qq] = g_Eq[((b * QQ) + q0 + qq) * HH + h];
    }
    __syncthreads();

    // ---- main loop: scores ----
    for (int kbase = 0; kbase < len; kbase += 512) {
        int k0 = kbase + tid * 2;
        if (k0 < len) {
            float accx[2] = {0.f, 0.f};     // k0,   q=0/1
            float accy[2] = {0.f, 0.f};     // k0+1, q=0/1
            const float* ekb = g_EkT + ((size_t)b * HH) * KK + k0;
#pragma unroll 4
            for (int h = 0; h < HH; h += 2) {
                float2 ekA = *(const float2*)(ekb + h * KK);
                float2 ekB = *(const float2*)(ekb + (h + 1) * KK);
                float2 eqA = *(const float2*)s_eq[h];
                float2 eqB = *(const float2*)s_eq[h + 1];
                float2 w   = *(const float2*)&s_w2[h];
#pragma unroll
                for (int qq = 0; qq < 2; qq++) {
                    float eqa = qq ? eqA.y : eqA.x;
                    float eqb = qq ? eqB.y : eqB.x;
                    float E1 = fmaf(ekA.x, eqa, 1.0f);
                    float E2 = fmaf(ekB.x, eqb, 1.0f);
                    float num = fmaf(w.x, E2, w.y * E1);
                    accx[qq] = fmaf(num, frcp(E1 * E2), accx[qq]);
                    float F1 = fmaf(ekA.y, eqa, 1.0f);
                    float F2 = fmaf(ekB.y, eqb, 1.0f);
                    float num2 = fmaf(w.x, F2, w.y * F1);
                    accy[qq] = fmaf(num2, frcp(F1 * F2), accy[qq]);
                }
            }
            float4 sc = make_float4(accx[0], accx[1], accy[0], accy[1]);
            *(float4*)&s_scores[k0 * 2] = sc;   // [k0][q0..1], [k0+1][q0..1]
        }
    }
    __syncthreads();

    // ---- masked softmax over k < len (unnormalized; denom folded later) ----
    int warp = tid >> 5, lane = tid & 31;
    float mx[2] = {-3.0e38f, -3.0e38f};
    for (int k = tid; k < len; k += 256) {
        float2 sc = *(const float2*)&s_scores[k * 2];
        mx[0] = fmaxf(mx[0], sc.x); mx[1] = fmaxf(mx[1], sc.y);
    }
#pragma unroll
    for (int qq = 0; qq < 2; qq++)
        for (int o = 16; o > 0; o >>= 1)
            mx[qq] = fmaxf(mx[qq], __shfl_xor_sync(0xffffffffu, mx[qq], o));
    if (lane == 0) { s_red[warp][0] = mx[0]; s_red[warp][1] = mx[1]; }
    __syncthreads();
    if (tid < 2) {
        float m = s_red[0][tid];
        for (int w = 1; w < 8; w++) m = fmaxf(m, s_red[w][tid]);
        s_mx[tid] = m;
    }
    __syncthreads();

    float sm[2] = {0.f, 0.f};
    float m0 = s_mx[0], m1 = s_mx[1];
    for (int k = tid; k < len; k += 256) {
        float2 sc = *(const float2*)&s_scores[k * 2];
        sc.x = fex2((sc.x - m0) * LOG2E);
        sc.y = fex2((sc.y - m1) * LOG2E);
        sm[0] += sc.x; sm[1] += sc.y;
        *(float2*)&s_scores[k * 2] = sc;
    }
#pragma unroll
    for (int qq = 0; qq < 2; qq++)
        for (int o = 16; o > 0; o >>= 1)
            sm[qq] += __shfl_xor_sync(0xffffffffu, sm[qq], o);
    if (lane == 0) { s_red[warp][0] = sm[0]; s_red[warp][1] = sm[1]; }
    __syncthreads();
    if (tid < 2) {
        float s = 0.f;
        for (int w = 0; w < 8; w++) s += s_red[w][tid];
        s_rden[tid] = frcp(s);
    }
    __syncthreads();

    // ---- attn @ V  (k split into 4 strided groups, reduce via smem) ----
    int g = tid >> 6;          // k-group
    int l = tid & 63;          // v pair index: v0 = 2*l
    float2 a0 = make_float2(0.f, 0.f);
    float2 a1 = make_float2(0.f, 0.f);
    const float2* Vp = (const float2*)(values + (size_t)b * KK * DVV);
    for (int k = g; k < len; k += 4) {
        float2 p = *(const float2*)&s_scores[k * 2];
        float2 v = Vp[k * (DVV / 2) + l];
        a0.x = fmaf(p.x, v.x, a0.x); a0.y = fmaf(p.x, v.y, a0.y);
        a1.x = fmaf(p.y, v.x, a1.x); a1.y = fmaf(p.y, v.y, a1.y);
    }
    *(float2*)&s_part[g][0][2 * l] = a0;
    *(float2*)&s_part[g][1][2 * l] = a1;
    __syncthreads();

    // final combine: thread t -> (q = t>>7, v = t&127)
    {
        int qq = tid >> 7;
        int v  = tid & 127;
        float rd = s_rden[qq];
        float o = s_part[0][qq][v] + s_part[1][qq][v]
                + s_part[2][qq][v] + s_part[3][qq][v];
        out[((size_t)(b * QQ + q0 + qq)) * DVV + v] = o * rd;
    }
}

extern "C" void kernel_launch(void* const* d_in, const int* in_sizes, int n_in,
                              void* d_out, int out_size) {
    const float* queries = (const float*)d_in[0];   // [8,256,256]
    const float* keys    = (const float*)d_in[1];   // [8,1024,256]
    const float* values  = (const float*)d_in[2];   // [8,1024,128]
    const int*   vlens   = (const int*)  d_in[3];   // [8]
    const float* W_q     = (const float*)d_in[4];   // [256,128]
    const float* W_k     = (const float*)d_in[5];   // [256,128]
    const float* w_v     = (const float*)d_in[6];   // [128]
    float* out = (float*)d_out;                     // [8,256,128]

    proj_kernel<<<(BB * QQ + BB * KK) / 8, 128>>>(queries, keys, W_q, W_k);
    attn_kernel<<<BB * (QQ / 2), 256>>>(values, vlens, w_v, out);
}

// round 4
// speedup vs baseline: 1.8500x; 1.1695x over previous
#include <cuda_runtime.h>

#define BB   8
#define QQ   256
#define KK   1024
#define DD   256
#define HH   128
#define DVV  128
#define LOG2E 1.44269504088896340736f

// Scratch (allocation-free: device globals)
__device__ float g_Eq [BB * QQ * HH];  // [b][q][h]  = exp(2*qproj)
__device__ float g_EkT[BB * HH * KK];  // [b][h][k]  = exp(2*kproj), transposed

__device__ __forceinline__ float frcp(float x) {
    float r; asm("rcp.approx.f32 %0, %1;" : "=f"(r) : "f"(x)); return r;
}
__device__ __forceinline__ float fex2(float x) {
    float r; asm("ex2.approx.f32 %0, %1;" : "=f"(r) : "f"(x)); return r;
}

// ---------------------------------------------------------------------------
// Kernel 1: merged projection + exp. 16 rows per block (halves W traffic),
// thread = output column h; W read in native [d][h] layout (coalesced).
//   blocks [0,128)   : query rows -> g_Eq[row][h]
//   blocks [128,640) : key rows   -> g_EkT[b][h][k] (smem-transposed store)
// ---------------------------------------------------------------------------
#define PR 16
__global__ __launch_bounds__(128)
void proj_kernel(const float* __restrict__ Q, const float* __restrict__ Kx,
                 const float* __restrict__ Wq, const float* __restrict__ Wk) {
    __shared__ __align__(16) float xs[PR][DD];     // 16 input rows (16 KB)
    __shared__ float es[HH][PR + 1];               // padded transpose buffer
    int blk  = blockIdx.x;
    bool isK = blk >= (BB * QQ) / PR;              // >= 128
    int rowbase = isK ? (blk - (BB * QQ) / PR) * PR : blk * PR;
    const float* X = isK ? Kx : Q;
    const float* W = isK ? Wk : Wq;
    int tid = threadIdx.x;                          // 0..127 (= h)

    {   // coalesced float4 row load
        const float4* Xp = (const float4*)(X + (size_t)rowbase * DD);
        float4* xsp = (float4*)xs;
        for (int i = tid; i < PR * DD / 4; i += 128) xsp[i] = Xp[i];
    }
    __syncthreads();

    float acc[PR];
#pragma unroll
    for (int r = 0; r < PR; r++) acc[r] = 0.f;

#pragma unroll 2
    for (int d4 = 0; d4 < DD / 4; d4++) {
        int d = d4 * 4;
        float w0 = W[(d + 0) * HH + tid];          // coalesced across warp
        float w1 = W[(d + 1) * HH + tid];
        float w2 = W[(d + 2) * HH + tid];
        float w3 = W[(d + 3) * HH + tid];
#pragma unroll
        for (int r = 0; r < PR; r++) {
            float4 x = *(const float4*)&xs[r][d];  // broadcast LDS.128
            acc[r] = fmaf(x.x, w0, acc[r]);
            acc[r] = fmaf(x.y, w1, acc[r]);
            acc[r] = fmaf(x.z, w2, acc[r]);
            acc[r] = fmaf(x.w, w3, acc[r]);
        }
    }

    if (!isK) {
#pragma unroll
        for (int r = 0; r < PR; r++)
            g_Eq[(rowbase + r) * HH + tid] = fex2(acc[r] * (2.0f * LOG2E));
    } else {
#pragma unroll
        for (int r = 0; r < PR; r++)
            es[tid][r] = fex2(acc[r] * (2.0f * LOG2E));
        __syncthreads();
        int b  = rowbase >> 10;
        int k0 = rowbase & 1023;
        for (int i = tid; i < HH * PR; i += 128) {
            int h = i >> 4, r = i & (PR - 1);
            g_EkT[((size_t)b * HH + h) * KK + k0 + r] = es[h][r];
        }
    }
}

// ---------------------------------------------------------------------------
// Kernel 2: fused scores + masked softmax + attn@V.
// Block = (b, tile of 2 q-rows), 1024 blocks, 256 threads.
// score contribution: -sum_h (2 w_h) * rcp(1 + Eq*Ek)  (constant wsum term
// cancels in softmax). h-pairing halves MUFU load.
// Inner loop software-pipelined: next 4-h ek batch prefetched (MLP>=4).
// ---------------------------------------------------------------------------
__global__ __launch_bounds__(256)
void attn_kernel(const float* __restrict__ values,
                 const int*   __restrict__ valid_lens,
                 const float* __restrict__ w_v,
                 float*       __restrict__ out) {
    __shared__ __align__(16) float s_eq[HH][2];        // [h][q]
    __shared__ __align__(16) float s_w2[HH];           // -2*w_v[h]
    __shared__ __align__(16) float s_scores[KK * 2];   // [k][q]
    __shared__ __align__(16) float s_part[4][2][DVV];  // [kgroup][q][v]
    __shared__ float s_red[8][2];
    __shared__ float s_mx[2];
    __shared__ float s_rden[2];

    int b  = blockIdx.x & 7;
    int q0 = (blockIdx.x >> 3) * 2;
    int tid = threadIdx.x;
    int len = valid_lens[b];

    if (tid < HH) s_w2[tid] = -2.0f * w_v[tid];
    if (tid < 2 * HH) {
        int qq = tid >> 7, h = tid & 127;
        s_eq[h][qq] = g_Eq[((b * QQ) + q0 + qq) * HH + h];
    }
    __syncthreads();

    // ---- main loop: scores (k chunks of 512, 2 k/thread, prefetched) ----
    for (int kbase = 0; kbase < len; kbase += 512) {
        int k0 = kbase + tid * 2;
        if (k0 < len) {
            float aA0 = 0.f, aA1 = 0.f, aB0 = 0.f, aB1 = 0.f; // [k][q]
            const float* ekb = g_EkT + ((size_t)b * HH) * KK + k0;
            float2 e0 = *(const float2*)(ekb);
            float2 e1 = *(const float2*)(ekb + KK);
            float2 e2 = *(const float2*)(ekb + 2 * KK);
            float2 e3 = *(const float2*)(ekb + 3 * KK);
#pragma unroll 2
            for (int h = 0; h < HH; h += 4) {
                float2 c0 = e0, c1 = e1, c2 = e2, c3 = e3;
                int hn = (h + 4) & (HH - 1);          // wrap: harmless reload
                e0 = *(const float2*)(ekb + (size_t)hn * KK);
                e1 = *(const float2*)(ekb + (size_t)(hn + 1) * KK);
                e2 = *(const float2*)(ekb + (size_t)(hn + 2) * KK);
                e3 = *(const float2*)(ekb + (size_t)(hn + 3) * KK);
                float4 eqA = *(const float4*)&s_eq[h][0];     // h,h+1 x q0,q1
                float4 eqB = *(const float4*)&s_eq[h + 2][0]; // h+2,h+3
                float4 w   = *(const float4*)&s_w2[h];
                // pair (h, h+1)
                {
                    float E1, E2, num;
                    E1 = fmaf(c0.x, eqA.x, 1.f); E2 = fmaf(c1.x, eqA.z, 1.f);
                    num = fmaf(w.x, E2, w.y * E1);
                    aA0 = fmaf(num, frcp(E1 * E2), aA0);
                    E1 = fmaf(c0.x, eqA.y, 1.f); E2 = fmaf(c1.x, eqA.w, 1.f);
                    num = fmaf(w.x, E2, w.y * E1);
                    aA1 = fmaf(num, frcp(E1 * E2), aA1);
                    E1 = fmaf(c0.y, eqA.x, 1.f); E2 = fmaf(c1.y, eqA.z, 1.f);
                    num = fmaf(w.x, E2, w.y * E1);
                    aB0 = fmaf(num, frcp(E1 * E2), aB0);
                    E1 = fmaf(c0.y, eqA.y, 1.f); E2 = fmaf(c1.y, eqA.w, 1.f);
                    num = fmaf(w.x, E2, w.y * E1);
                    aB1 = fmaf(num, frcp(E1 * E2), aB1);
                }
                // pair (h+2, h+3)
                {
                    float E1, E2, num;
                    E1 = fmaf(c2.x, eqB.x, 1.f); E2 = fmaf(c3.x, eqB.z, 1.f);
                    num = fmaf(w.z, E2, w.w * E1);
                    aA0 = fmaf(num, frcp(E1 * E2), aA0);
                    E1 = fmaf(c2.x, eqB.y, 1.f); E2 = fmaf(c3.x, eqB.w, 1.f);
                    num = fmaf(w.z, E2, w.w * E1);
                    aA1 = fmaf(num, frcp(E1 * E2), aA1);
                    E1 = fmaf(c2.y, eqB.x, 1.f); E2 = fmaf(c3.y, eqB.z, 1.f);
                    num = fmaf(w.z, E2, w.w * E1);
                    aB0 = fmaf(num, frcp(E1 * E2), aB0);
                    E1 = fmaf(c2.y, eqB.y, 1.f); E2 = fmaf(c3.y, eqB.w, 1.f);
                    num = fmaf(w.z, E2, w.w * E1);
                    aB1 = fmaf(num, frcp(E1 * E2), aB1);
                }
            }
            *(float4*)&s_scores[k0 * 2] = make_float4(aA0, aA1, aB0, aB1);
        }
    }
    __syncthreads();

    // ---- masked softmax over k < len (unnormalized; denom folded later) ----
    int warp = tid >> 5, lane = tid & 31;
    float mx[2] = {-3.0e38f, -3.0e38f};
    for (int k = tid; k < len; k += 256) {
        float2 sc = *(const float2*)&s_scores[k * 2];
        mx[0] = fmaxf(mx[0], sc.x); mx[1] = fmaxf(mx[1], sc.y);
    }
#pragma unroll
    for (int qq = 0; qq < 2; qq++)
        for (int o = 16; o > 0; o >>= 1)
            mx[qq] = fmaxf(mx[qq], __shfl_xor_sync(0xffffffffu, mx[qq], o));
    if (lane == 0) { s_red[warp][0] = mx[0]; s_red[warp][1] = mx[1]; }
    __syncthreads();
    if (tid < 2) {
        float m = s_red[0][tid];
        for (int w = 1; w < 8; w++) m = fmaxf(m, s_red[w][tid]);
        s_mx[tid] = m;
    }
    __syncthreads();

    float sm[2] = {0.f, 0.f};
    float m0 = s_mx[0], m1 = s_mx[1];
    for (int k = tid; k < len; k += 256) {
        float2 sc = *(const float2*)&s_scores[k * 2];
        sc.x = fex2((sc.x - m0) * LOG2E);
        sc.y = fex2((sc.y - m1) * LOG2E);
        sm[0] += sc.x; sm[1] += sc.y;
        *(float2*)&s_scores[k * 2] = sc;
    }
#pragma unroll
    for (int qq = 0; qq < 2; qq++)
        for (int o = 16; o > 0; o >>= 1)
            sm[qq] += __shfl_xor_sync(0xffffffffu, sm[qq], o);
    if (lane == 0) { s_red[warp][0] = sm[0]; s_red[warp][1] = sm[1]; }
    __syncthreads();
    if (tid < 2) {
        float s = 0.f;
        for (int w = 0; w < 8; w++) s += s_red[w][tid];
        s_rden[tid] = frcp(s);
    }
    __syncthreads();

    // ---- attn @ V  (k split into 4 strided groups, reduce via smem) ----
    int g = tid >> 6;          // k-group
    int l = tid & 63;          // v pair index: v0 = 2*l
    float2 a0 = make_float2(0.f, 0.f);
    float2 a1 = make_float2(0.f, 0.f);
    const float2* Vp = (const float2*)(values + (size_t)b * KK * DVV);
    for (int k = g; k < len; k += 4) {
        float2 p = *(const float2*)&s_scores[k * 2];
        float2 v = Vp[k * (DVV / 2) + l];
        a0.x = fmaf(p.x, v.x, a0.x); a0.y = fmaf(p.x, v.y, a0.y);
        a1.x = fmaf(p.y, v.x, a1.x); a1.y = fmaf(p.y, v.y, a1.y);
    }
    *(float2*)&s_part[g][0][2 * l] = a0;
    *(float2*)&s_part[g][1][2 * l] = a1;
    __syncthreads();

    {
        int qq = tid >> 7;
        int v  = tid & 127;
        float rd = s_rden[qq];
        float o = s_part[0][qq][v] + s_part[1][qq][v]
                + s_part[2][qq][v] + s_part[3][qq][v];
        out[((size_t)(b * QQ + q0 + qq)) * DVV + v] = o * rd;
    }
}

extern "C" void kernel_launch(void* const* d_in, const int* in_sizes, int n_in,
                              void* d_out, int out_size) {
    const float* queries = (const float*)d_in[0];   // [8,256,256]
    const float* keys    = (const float*)d_in[1];   // [8,1024,256]
    const float* values  = (const float*)d_in[2];   // [8,1024,128]
    const int*   vlens   = (const int*)  d_in[3];   // [8]
    const float* W_q     = (const float*)d_in[4];   // [256,128]
    const float* W_k     = (const float*)d_in[5];   // [256,128]
    const float* w_v     = (const float*)d_in[6];   // [128]
    float* out = (float*)d_out;                     // [8,256,128]

    proj_kernel<<<(BB * QQ + BB * KK) / PR, 128>>>(queries, keys, W_q, W_k);
    attn_kernel<<<BB * (QQ / 2), 256>>>(values, vlens, w_v, out);
}

// round 5
// speedup vs baseline: 2.1322x; 1.1525x over previous
#include <cuda_runtime.h>

#define BB   8
#define QQ   256
#define KK   1024
#define DD   256
#define HH   128
#define DVV  128
#define LOG2E 1.44269504088896340736f

// Scratch (allocation-free: device globals)
__device__ float g_Eq [BB * QQ * HH];        // [b][q][h]   = exp(2*qproj)
__device__ float g_Ek4[BB * (HH/4) * KK * 4];// [b][h/4][k][4] = exp(2*kproj)

__device__ __forceinline__ float frcp(float x) {
    float r; asm("rcp.approx.f32 %0, %1;" : "=f"(r) : "f"(x)); return r;
}
__device__ __forceinline__ float fex2(float x) {
    float r; asm("ex2.approx.f32 %0, %1;" : "=f"(r) : "f"(x)); return r;
}

// ---------------------------------------------------------------------------
// Kernel 1: merged projection + exp. 16 rows per block, thread = column h.
// W read in native [d][h] layout (coalesced), prefetched one quad ahead.
//   blocks [0,128)   : query rows -> g_Eq[row][h]
//   blocks [128,640) : key rows   -> g_Ek4[b][h/4][k][4] (interleaved)
// ---------------------------------------------------------------------------
#define PR 16
__global__ __launch_bounds__(128)
void proj_kernel(const float* __restrict__ Q, const float* __restrict__ Kx,
                 const float* __restrict__ Wq, const float* __restrict__ Wk) {
    __shared__ __align__(16) float xs[PR][DD];     // 16 input rows (16 KB)
    __shared__ float es[HH][PR + 1];               // padded transpose buffer
    int blk  = blockIdx.x;
    bool isK = blk >= (BB * QQ) / PR;              // >= 128
    int rowbase = isK ? (blk - (BB * QQ) / PR) * PR : blk * PR;
    const float* X = isK ? Kx : Q;
    const float* W = isK ? Wk : Wq;
    int tid = threadIdx.x;                          // 0..127 (= h)

    {   // coalesced float4 row load
        const float4* Xp = (const float4*)(X + (size_t)rowbase * DD);
        float4* xsp = (float4*)xs;
        for (int i = tid; i < PR * DD / 4; i += 128) xsp[i] = Xp[i];
    }
    __syncthreads();

    float acc[PR];
#pragma unroll
    for (int r = 0; r < PR; r++) acc[r] = 0.f;

    const float* Wp = W + tid;
    float w0 = Wp[0 * HH], w1 = Wp[1 * HH], w2 = Wp[2 * HH], w3 = Wp[3 * HH];
    for (int d4 = 0; d4 < DD / 4; d4++) {
        float c0 = w0, c1 = w1, c2 = w2, c3 = w3;
        if (d4 + 1 < DD / 4) {                     // prefetch next W quad
            const float* Wn = Wp + (d4 + 1) * 4 * HH;
            w0 = Wn[0 * HH]; w1 = Wn[1 * HH]; w2 = Wn[2 * HH]; w3 = Wn[3 * HH];
        }
        int d = d4 * 4;
#pragma unroll
        for (int r = 0; r < PR; r++) {
            float4 x = *(const float4*)&xs[r][d];  // broadcast LDS.128
            acc[r] = fmaf(x.x, c0, acc[r]);
            acc[r] = fmaf(x.y, c1, acc[r]);
            acc[r] = fmaf(x.z, c2, acc[r]);
            acc[r] = fmaf(x.w, c3, acc[r]);
        }
    }

    if (!isK) {
#pragma unroll
        for (int r = 0; r < PR; r++)
            g_Eq[(rowbase + r) * HH + tid] = fex2(acc[r] * (2.0f * LOG2E));
    } else {
#pragma unroll
        for (int r = 0; r < PR; r++)
            es[tid][r] = fex2(acc[r] * (2.0f * LOG2E));
        __syncthreads();
        int b  = rowbase >> 10;
        int k0 = rowbase & 1023;
        // interleaved store: [hq][k][h%4], consecutive i -> consecutive addr
        for (int i = tid; i < HH * PR; i += 128) {
            int hq = i >> 6;              // 64 = PR*4 elements per h-quad
            int r  = (i >> 2) & (PR - 1);
            int h2 = i & 3;
            g_Ek4[(((size_t)b * (HH/4) + hq) * KK + k0 + r) * 4 + h2]
                = es[hq * 4 + h2][r];
        }
    }
}

// ---------------------------------------------------------------------------
// Kernel 2: fused scores + exp + softmax-denominator + attn@V.
// Block = (b, tile of 2 q-rows), 1024 blocks, 256 threads.
// score (up to the constant wsum, which cancels in softmax):
//   s = sum_h (-2 w_h) * rcp(1 + Eq*Ek)
// |s| <= 2*sum|w_h| (~18) -> exp without max subtraction is fp32-safe.
// exp fused into the score loop; denom accumulated in registers.
// Ek loads: LDG.128 per (4h,k), prefetch depth 2 (4 loads in flight).
// ---------------------------------------------------------------------------
__global__ __launch_bounds__(256)
void attn_kernel(const float* __restrict__ values,
                 const int*   __restrict__ valid_lens,
                 const float* __restrict__ w_v,
                 float*       __restrict__ out) {
    __shared__ __align__(16) float s_eq[HH][2];        // [h][q]
    __shared__ __align__(16) float s_w2[HH];           // -2*w_v[h]
    __shared__ __align__(16) float s_scores[KK * 2];   // exp'ed probs [k][q]
    __shared__ __align__(16) float s_part[4][2][DVV];  // [kgroup][q][v]
    __shared__ float s_red[8][2];
    __shared__ float s_rden[2];

    int b  = blockIdx.x & 7;
    int q0 = (blockIdx.x >> 3) * 2;
    int tid = threadIdx.x;
    int len = valid_lens[b];

    if (tid < HH) s_w2[tid] = -2.0f * w_v[tid];
    if (tid < 2 * HH) {
        int qq = tid >> 7, h = tid & 127;
        s_eq[h][qq] = g_Eq[((b * QQ) + q0 + qq) * HH + h];
    }
    __syncthreads();

    float sum0 = 0.f, sum1 = 0.f;   // denominator partials (q0, q1)

    // ---- main loop: scores + exp (k chunks of 512, 2 k per thread) ----
    for (int kbase = 0; kbase < len; kbase += 512) {
        int k0 = kbase + tid * 2;
        if (k0 < len) {
            float aA0 = 0.f, aA1 = 0.f, aB0 = 0.f, aB1 = 0.f; // [k][q]
            // float4 view: index = hq*KK + k
            const float4* ek4 = (const float4*)g_Ek4 + (size_t)b * (HH/4) * KK + k0;
            float4 p0a = ek4[0];            // hq=0, k0
            float4 p0b = ek4[1];            // hq=0, k0+1
            float4 p1a = ek4[KK];           // hq=1, k0
            float4 p1b = ek4[KK + 1];       // hq=1, k0+1
#pragma unroll 2
            for (int hq = 0; hq < HH / 4; hq++) {
                float4 ca = p0a, cb = p0b;
                p0a = p1a; p0b = p1b;
                int hn = (hq + 2) & (HH / 4 - 1);     // wrap: harmless reload
                p1a = ek4[(size_t)hn * KK];
                p1b = ek4[(size_t)hn * KK + 1];
                int h = hq * 4;
                float4 eqA = *(const float4*)&s_eq[h][0];     // h,h+1 x q0,q1
                float4 eqB = *(const float4*)&s_eq[h + 2][0]; // h+2,h+3
                float4 w   = *(const float4*)&s_w2[h];
                float E1, E2, num;
                // pair (h, h+1): components .x/.y of ca,cb
                E1 = fmaf(ca.x, eqA.x, 1.f); E2 = fmaf(ca.y, eqA.z, 1.f);
                num = fmaf(w.x, E2, w.y * E1);
                aA0 = fmaf(num, frcp(E1 * E2), aA0);
                E1 = fmaf(ca.x, eqA.y, 1.f); E2 = fmaf(ca.y, eqA.w, 1.f);
                num = fmaf(w.x, E2, w.y * E1);
                aA1 = fmaf(num, frcp(E1 * E2), aA1);
                E1 = fmaf(cb.x, eqA.x, 1.f); E2 = fmaf(cb.y, eqA.z, 1.f);
                num = fmaf(w.x, E2, w.y * E1);
                aB0 = fmaf(num, frcp(E1 * E2), aB0);
                E1 = fmaf(cb.x, eqA.y, 1.f); E2 = fmaf(cb.y, eqA.w, 1.f);
                num = fmaf(w.x, E2, w.y * E1);
                aB1 = fmaf(num, frcp(E1 * E2), aB1);
                // pair (h+2, h+3): components .z/.w
                E1 = fmaf(ca.z, eqB.x, 1.f); E2 = fmaf(ca.w, eqB.z, 1.f);
                num = fmaf(w.z, E2, w.w * E1);
                aA0 = fmaf(num, frcp(E1 * E2), aA0);
                E1 = fmaf(ca.z, eqB.y, 1.f); E2 = fmaf(ca.w, eqB.w, 1.f);
                num = fmaf(w.z, E2, w.w * E1);
                aA1 = fmaf(num, frcp(E1 * E2), aA1);
                E1 = fmaf(cb.z, eqB.x, 1.f); E2 = fmaf(cb.w, eqB.z, 1.f);
                num = fmaf(w.z, E2, w.w * E1);
                aB0 = fmaf(num, frcp(E1 * E2), aB0);
                E1 = fmaf(cb.z, eqB.y, 1.f); E2 = fmaf(cb.w, eqB.w, 1.f);
                num = fmaf(w.z, E2, w.w * E1);
                aB1 = fmaf(num, frcp(E1 * E2), aB1);
            }
            // exp (no max subtraction needed: |score| <= ~18)
            float pA0 = fex2(aA0 * LOG2E);
            float pA1 = fex2(aA1 * LOG2E);
            float pB0 = fex2(aB0 * LOG2E);
            float pB1 = fex2(aB1 * LOG2E);
            *(float4*)&s_scores[k0 * 2] = make_float4(pA0, pA1, pB0, pB1);
            bool two = (k0 + 1 < len);
            if (!two) { pB0 = 0.f; pB1 = 0.f; }   // guard odd len tail
            sum0 += pA0 + pB0;
            sum1 += pA1 + pB1;
        }
    }
    // NOTE: if len is odd, s_scores[len] was written but AV reads only k<len.

    // ---- denominator reduction ----
    int warp = tid >> 5, lane = tid & 31;
    for (int o = 16; o > 0; o >>= 1) {
        sum0 += __shfl_xor_sync(0xffffffffu, sum0, o);
        sum1 += __shfl_xor_sync(0xffffffffu, sum1, o);
    }
    if (lane == 0) { s_red[warp][0] = sum0; s_red[warp][1] = sum1; }
    __syncthreads();
    if (tid < 2) {
        float s = 0.f;
        for (int w = 0; w < 8; w++) s += s_red[w][tid];
        s_rden[tid] = frcp(s);
    }
    __syncthreads();

    // ---- attn @ V  (k split into 4 strided groups, reduce via smem) ----
    int g = tid >> 6;          // k-group
    int l = tid & 63;          // v pair index: v0 = 2*l
    float2 a0 = make_float2(0.f, 0.f);
    float2 a1 = make_float2(0.f, 0.f);
    const float2* Vp = (const float2*)(values + (size_t)b * KK * DVV);
    for (int k = g; k < len; k += 4) {
        float2 p = *(const float2*)&s_scores[k * 2];
        float2 v = Vp[k * (DVV / 2) + l];
        a0.x = fmaf(p.x, v.x, a0.x); a0.y = fmaf(p.x, v.y, a0.y);
        a1.x = fmaf(p.y, v.x, a1.x); a1.y = fmaf(p.y, v.y, a1.y);
    }
    *(float2*)&s_part[g][0][2 * l] = a0;
    *(float2*)&s_part[g][1][2 * l] = a1;
    __syncthreads();

    {
        int qq = tid >> 7;
        int v  = tid & 127;
        float rd = s_rden[qq];
        float o = s_part[0][qq][v] + s_part[1][qq][v]
                + s_part[2][qq][v] + s_part[3][qq][v];
        out[((size_t)(b * QQ + q0 + qq)) * DVV + v] = o * rd;
    }
}

extern "C" void kernel_launch(void* const* d_in, const int* in_sizes, int n_in,
                              void* d_out, int out_size) {
    const float* queries = (const float*)d_in[0];   // [8,256,256]
    const float* keys    = (const float*)d_in[1];   // [8,1024,256]
    const float* values  = (const float*)d_in[2];   // [8,1024,128]
    const int*   vlens   = (const int*)  d_in[3];   // [8]
    const float* W_q     = (const float*)d_in[4];   // [256,128]
    const float* W_k     = (const float*)d_in[5];   // [256,128]
    const float* w_v     = (const float*)d_in[6];   // [128]
    float* out = (float*)d_out;                     // [8,256,128]

    proj_kernel<<<(BB * QQ + BB * KK) / PR, 128>>>(queries, keys, W_q, W_k);
    attn_kernel<<<BB * (QQ / 2), 256>>>(values, vlens, w_v, out);
}